// round 16
// baseline (speedup 1.0000x reference)
#include <cuda_runtime.h>
#include <cuda_bf16.h>

// ConvTreeBlock: N=1e6 nodes, C=16, KS=9.
// R16 = channel-split accumulation:
//  - quad (4 lanes) owns a node; lane q loads row quarter [4q,4q+4) with ONE
//    LDG.128 -> 1 gather wavefront/node-j (hardware minimum), halved vs R10.
//  - NO per-j exchange: lane accumulates ALL 16 outputs for its 4 channels;
//    quad butterfly-reduces accumulators ONCE at the end (static indices only).
//  - 4 nodes per thread (R15-proven-safe) amortize weight LDS + loop overhead.
//  - weights in TWO smem copies, 8-float phase shift -> 4 distinct bank groups
//    (kills the R9 conflict). f32x2 FMA kept. Fused stats + BN1-in-gather kept.
// Launches: zero_stats -> conv1(+stats1) -> conv2(BN1+leaky inline, +stats2) -> bnact2.

#define NMAX 1000000

__device__ float g_y1[(size_t)NMAX * 16];   // conv1 raw output (device-side only!)
__device__ float g_stats[64];               // [0:16]sum1 [16:32]ssq1 [32:48]sum2 [48:64]ssq2

static constexpr float EPS   = 1e-5f;
static constexpr float SLOPE = 0.2f;

// ---- f32x2 helpers (exact fp32 semantics, 2 MACs/instr) ----
__device__ __forceinline__ unsigned long long dup2(float x) {
    unsigned long long r;
    asm("mov.b64 %0, {%1, %1};" : "=l"(r) : "f"(x));
    return r;
}
__device__ __forceinline__ void fma2(unsigned long long& acc, unsigned long long a, unsigned long long b) {
    asm("fma.rn.f32x2 %0, %1, %2, %0;" : "+l"(acc) : "l"(a), "l"(b));
}
__device__ __forceinline__ unsigned long long add2(unsigned long long a, unsigned long long b) {
    unsigned long long r;
    asm("add.rn.f32x2 %0, %1, %2;" : "=l"(r) : "l"(a), "l"(b));
    return r;
}
__device__ __forceinline__ void unpack2(unsigned long long v, float& lo, float& hi) {
    asm("mov.b64 {%0, %1}, %2;" : "=f"(lo), "=f"(hi) : "l"(v));
}

__global__ void k_zero_stats()
{
    if (threadIdx.x < 64) g_stats[threadIdx.x] = 0.0f;
}

// Weight smem layout: ws[j*320 + c*20 + o], o=0..15 (stride 20 floats = 80B,
// 16B-aligned). Two copies phase-shifted by 8 floats (wsB = wsA + 2888) so the
// four lane channel-bases {0,80,160,240}(+8 for q>=2) land in 4 distinct bank
// quads: {0-3, 16-19, 8-11, 24-27}.
#define WJ 320
#define WTOT (9 * WJ)   // 2880

template<int LAYER>
__global__ __launch_bounds__(256, 1)
void k_conv(const float* __restrict__ src_param,  // LAYER1: data
            const int*   __restrict__ ind,
            const float* __restrict__ w,          // [c][o][j] : c*144 + o*9 + j
            const float* __restrict__ bias,       // LAYER1 only
            const float* __restrict__ gamma,      // LAYER2: gamma1
            const float* __restrict__ beta,       // LAYER2: beta1
            float*       __restrict__ dst_param,  // LAYER2: d_out
            int n, int stat_off_in, int stat_off_out)
{
    // device-side scratch selection (NEVER pass __device__ symbols from host)
    const float* src = (LAYER == 1) ? src_param : (const float*)g_y1;
    float*       dst = (LAYER == 1) ? (float*)g_y1 : dst_param;

    __shared__ __align__(16) float wsA[WTOT];
    __shared__ float pad8[8];                  // phase shift: wsB base = wsA+2888 == +8 mod 32
    __shared__ __align__(16) float wsB[WTOT];
    __shared__ float s_ab[32];                 // a[16], b[16] (LAYER 2)
    __shared__ float s_stat[32];               // sum[16], ssq[16]

    const int tid = threadIdx.x;
    (void)pad8;

    for (int s = tid; s < 2304; s += 256) {
        int o = s & 15, c = (s >> 4) & 15, j = s >> 8;
        float v = w[c * 144 + o * 9 + j];
        wsA[j * WJ + c * 20 + o] = v;
        wsB[j * WJ + c * 20 + o] = v;
    }
    if (tid < 32) s_stat[tid] = 0.0f;
    if (LAYER == 2 && tid < 16) {
        float inv  = 1.0f / (float)n;
        float mean = g_stats[stat_off_in + tid] * inv;
        float var  = g_stats[stat_off_in + 16 + tid] * inv - mean * mean;
        float a    = gamma[tid] * rsqrtf(var + EPS);
        s_ab[tid]      = a;
        s_ab[16 + tid] = beta[tid] - a * mean;
    }
    __syncthreads();

    const int q    = tid & 3;                  // lane's channel quarter [4q,4q+4)
    const int quad = tid >> 2;                 // 0..63
    const int oq   = q * 4;

    int  nodeN[4]; bool actN[4]; int ibase[4];
#pragma unroll
    for (int m = 0; m < 4; ++m) {
        nodeN[m] = blockIdx.x * 256 + m * 64 + quad;
        actN[m]  = nodeN[m] < n;
        ibase[m] = actN[m] ? nodeN[m] * 9 : 0;
    }

    unsigned long long acc[4][8];
#pragma unroll
    for (int m = 0; m < 4; ++m)
#pragma unroll
        for (int t = 0; t < 8; ++t) acc[m][t] = 0ULL;

    // lane's weight base: channels [4q,4q+4), conflict-free via dual copy
    const float* wbase = ((q & 2) ? wsB : wsA) + oq * 20;

    // software pipeline: prefetch quarter-rows for j+1 while computing j
    float4 cur[4];
#pragma unroll
    for (int m = 0; m < 4; ++m) {
        int r = ind[ibase[m]];
        cur[m] = *reinterpret_cast<const float4*>(src + (size_t)r * 16 + oq);
    }

#pragma unroll 1   // compact body; cross-warp MLP + 4-deep per-thread MLP hide L2
    for (int j = 0; j < 9; ++j) {
        float4 nxt[4];
        if (j < 8) {
#pragma unroll
            for (int m = 0; m < 4; ++m) {
                int r = ind[ibase[m] + j + 1];
                nxt[m] = *reinterpret_cast<const float4*>(src + (size_t)r * 16 + oq);
            }
        } else {
#pragma unroll
            for (int m = 0; m < 4; ++m) nxt[m] = make_float4(0.f, 0.f, 0.f, 0.f);
        }

        float own[4][4];
#pragma unroll
        for (int m = 0; m < 4; ++m) {
            own[m][0] = cur[m].x; own[m][1] = cur[m].y;
            own[m][2] = cur[m].z; own[m][3] = cur[m].w;
        }
        if (LAYER == 2) {
#pragma unroll
            for (int i = 0; i < 4; ++i) {
                float a = s_ab[oq + i], b = s_ab[16 + oq + i];
#pragma unroll
                for (int m = 0; m < 4; ++m) {
                    float v = fmaf(own[m][i], a, b);
                    own[m][i] = fmaxf(v, SLOPE * v);
                }
            }
        }

        const float* wj = wbase + j * WJ;
#pragma unroll
        for (int i = 0; i < 4; ++i) {          // input channel oq+i: 16-output row
            const float* wr = wj + i * 20;
            ulonglong2 w01 = *reinterpret_cast<const ulonglong2*>(wr);
            ulonglong2 w23 = *reinterpret_cast<const ulonglong2*>(wr + 4);
            ulonglong2 w45 = *reinterpret_cast<const ulonglong2*>(wr + 8);
            ulonglong2 w67 = *reinterpret_cast<const ulonglong2*>(wr + 12);
#pragma unroll
            for (int m = 0; m < 4; ++m) {
                unsigned long long x = dup2(own[m][i]);
                fma2(acc[m][0], x, w01.x); fma2(acc[m][1], x, w01.y);
                fma2(acc[m][2], x, w23.x); fma2(acc[m][3], x, w23.y);
                fma2(acc[m][4], x, w45.x); fma2(acc[m][5], x, w45.y);
                fma2(acc[m][6], x, w67.x); fma2(acc[m][7], x, w67.y);
            }
        }
#pragma unroll
        for (int m = 0; m < 4; ++m) cur[m] = nxt[m];
    }

    // ---- epilogue: quad butterfly reduce accumulators, store, fused stats ----
    const bool hi = (q & 2) != 0;
    const bool lo = (q & 1) != 0;
    float sv[4] = {0, 0, 0, 0}, qv[4] = {0, 0, 0, 0};

#pragma unroll
    for (int m = 0; m < 4; ++m) {
        // round 1 (xor 2): keep my 8-output half
        unsigned long long o1[8];
#pragma unroll
        for (int t = 0; t < 8; ++t)
            o1[t] = __shfl_xor_sync(0xFFFFFFFFu, acc[m][t], 2);
        unsigned long long kept[4];
#pragma unroll
        for (int t = 0; t < 4; ++t)
            kept[t] = hi ? add2(acc[m][t + 4], o1[t + 4]) : add2(acc[m][t], o1[t]);
        // round 2 (xor 1): keep my 4-output quarter
        unsigned long long o2[4];
#pragma unroll
        for (int t = 0; t < 4; ++t)
            o2[t] = __shfl_xor_sync(0xFFFFFFFFu, kept[t], 1);
        unsigned long long f0 = lo ? add2(kept[2], o2[2]) : add2(kept[0], o2[0]);
        unsigned long long f1 = lo ? add2(kept[3], o2[3]) : add2(kept[1], o2[1]);

        float ov[4];
        unpack2(f0, ov[0], ov[1]);
        unpack2(f1, ov[2], ov[3]);
        if (LAYER == 1) {
#pragma unroll
            for (int i = 0; i < 4; ++i) ov[i] += __ldg(bias + oq + i);
        }
        if (actN[m]) {
            *reinterpret_cast<float4*>(dst + (size_t)nodeN[m] * 16 + oq) =
                make_float4(ov[0], ov[1], ov[2], ov[3]);
#pragma unroll
            for (int i = 0; i < 4; ++i) { sv[i] += ov[i]; qv[i] += ov[i] * ov[i]; }
        }
    }

    // reduce stats over node lanes (xor 4,8,16 keep q in bits 0-1)
#pragma unroll
    for (int d = 4; d < 32; d <<= 1) {
#pragma unroll
        for (int k = 0; k < 4; ++k) {
            sv[k] += __shfl_xor_sync(0xFFFFFFFFu, sv[k], d);
            qv[k] += __shfl_xor_sync(0xFFFFFFFFu, qv[k], d);
        }
    }
    if ((tid & 31) < 4) {                      // lane L holds channels [4L,4L+4)
#pragma unroll
        for (int k = 0; k < 4; ++k) {
            atomicAdd(&s_stat[oq + k],      sv[k]);
            atomicAdd(&s_stat[16 + oq + k], qv[k]);
        }
    }
    __syncthreads();
    if (tid < 32) atomicAdd(&g_stats[stat_off_out + tid], s_stat[tid]);
}

// Final: out = leaky(a2[c]*y2 + b2[c] + data), in place on d_out.
__global__ __launch_bounds__(256)
void k_bnact2(const float* __restrict__ gamma,
              const float* __restrict__ beta,
              const float* __restrict__ res,
              float*       __restrict__ out,
              int n, int off)
{
    __shared__ float sa[16], sb[16];
    if (threadIdx.x < 16) {
        int c = threadIdx.x;
        float inv  = 1.0f / (float)n;
        float mean = g_stats[off + c] * inv;
        float var  = g_stats[off + 16 + c] * inv - mean * mean;
        float a    = gamma[c] * rsqrtf(var + EPS);
        sa[c] = a;
        sb[c] = beta[c] - a * mean;
    }
    __syncthreads();

    int n4 = n * 4;
    int stride = gridDim.x * 256;
    for (int i = blockIdx.x * 256 + threadIdx.x; i < n4; i += stride) {
        float4 v = reinterpret_cast<float4*>(out)[i];
        float4 r = reinterpret_cast<const float4*>(res)[i];
        int c0 = (i & 3) * 4;
        v.x = fmaf(v.x, sa[c0 + 0], sb[c0 + 0]) + r.x;  v.x = fmaxf(v.x, SLOPE * v.x);
        v.y = fmaf(v.y, sa[c0 + 1], sb[c0 + 1]) + r.y;  v.y = fmaxf(v.y, SLOPE * v.y);
        v.z = fmaf(v.z, sa[c0 + 2], sb[c0 + 2]) + r.z;  v.z = fmaxf(v.z, SLOPE * v.z);
        v.w = fmaf(v.w, sa[c0 + 3], sb[c0 + 3]) + r.w;  v.w = fmaxf(v.w, SLOPE * v.w);
        reinterpret_cast<float4*>(out)[i] = v;
    }
}

extern "C" void kernel_launch(void* const* d_in, const int* in_sizes, int n_in,
                              void* d_out, int out_size)
{
    const float* data   = (const float*)d_in[0];
    const int*   ind    = (const int*)  d_in[1];
    const float* w1     = (const float*)d_in[2];
    const float* b1     = (const float*)d_in[3];
    const float* gamma1 = (const float*)d_in[4];
    const float* beta1  = (const float*)d_in[5];
    const float* w2     = (const float*)d_in[6];
    const float* gamma2 = (const float*)d_in[7];
    const float* beta2  = (const float*)d_in[8];
    float*       out    = (float*)d_out;

    int n = in_sizes[0] / 16;
    if (n > NMAX) n = NMAX;

    int conv_blocks = (n + 255) / 256;   // 256 nodes per block (4 per thread)
    int ew_blocks   = 1184;

    k_zero_stats<<<1, 64>>>();
    k_conv<1><<<conv_blocks, 256>>>(data, ind, w1, b1, nullptr, nullptr, nullptr, n, 0, 0);
    k_conv<2><<<conv_blocks, 256>>>(nullptr, ind, w2, nullptr, gamma1, beta1, out, n, 0, 32);
    k_bnact2<<<ew_blocks, 256>>>(gamma2, beta2, data, out, n, 32);
}